// round 4
// baseline (speedup 1.0000x reference)
#include <cuda_runtime.h>
#include <math.h>
#include <limits.h>

// WARP loss: per-row rejection sampling over pre-drawn negative candidates.
// input  [B,Y] f32, target [B,Y] f32 (one-hot), neg_candidates [B,T] i32.
// out[0] = sum_b  L_b * (1 - s_pos + s_neg),  L_b = log((Y-1)/num_trials).
//
// R4: two-probe scan. Probe 1 = first 20KB of the row with ALL loads in
// flight (one DRAM round-trip, covers 51% of rows); probe 2 = the rest.
// Expected serialized rounds/CTA = 1.49 (vs ~5 in R3). Candidate gathers
// still issued first so their 2-deep chain overlaps probe 1.

#define NT 256
#define P1_VEC 5   // float4 per thread in probe 1: 256*5=1280 vec = 5120 floats

__global__ __launch_bounds__(NT, 8)
void warp_loss_kernel(const float* __restrict__ input,
                      const float* __restrict__ target,
                      const int*   __restrict__ neg,
                      float* __restrict__ out,
                      int Y, int T) {
    const int row  = blockIdx.x;
    const int tid  = threadIdx.x;
    const int lane = tid & 31;
    const int wid  = tid >> 5;
    const float* irow = input  + (size_t)row * Y;
    const float* trow = target + (size_t)row * Y;

    __shared__ float sc_sh[128];     // candidate scores
    __shared__ float s_pscore;       // score of positive label
    __shared__ int   s_first_w[4];   // per-warp first accepted trial

    // --- Phase 0: candidate gathers (independent of pos; overlap probe 1) ---
    float sc = 0.0f;
    if (tid < T) {
        const int c = __ldg(&neg[(size_t)row * T + tid]);
        sc = __ldg(&irow[c]);
        sc_sh[tid] = sc;
    }

    const int nvec = Y >> 2;                         // 2500 for Y=10000
    const float4* tv = reinterpret_cast<const float4*>(trow);
    const float4 zero4 = make_float4(0.f, 0.f, 0.f, 0.f);

    // --- Probe 1: first P1_VEC*NT float4 (20KB), all loads issued up front ---
    {
        float4 v[P1_VEC];
        int    idx[P1_VEC];
#pragma unroll
        for (int k = 0; k < P1_VEC; k++) {
            idx[k] = k * NT + tid;
            v[k] = (idx[k] < nvec) ? __ldg(&tv[idx[k]]) : zero4;
        }
        int p = -1;
#pragma unroll
        for (int k = 0; k < P1_VEC; k++) {
            if (v[k].x != 0.0f) p = 4 * idx[k];
            if (v[k].y != 0.0f) p = 4 * idx[k] + 1;
            if (v[k].z != 0.0f) p = 4 * idx[k] + 2;
            if (v[k].w != 0.0f) p = 4 * idx[k] + 3;
        }
        if (p >= 0) s_pscore = __ldg(&irow[p]);
        if (!__syncthreads_or(p >= 0)) {
            // --- Probe 2: remaining vectors (19KB), all loads up front ---
            float4 w[P1_VEC];
            int    jdx[P1_VEC];
#pragma unroll
            for (int k = 0; k < P1_VEC; k++) {
                jdx[k] = (P1_VEC + k) * NT + tid;
                w[k] = (jdx[k] < nvec) ? __ldg(&tv[jdx[k]]) : zero4;
            }
            int q = -1;
#pragma unroll
            for (int k = 0; k < P1_VEC; k++) {
                if (w[k].x != 0.0f) q = 4 * jdx[k];
                if (w[k].y != 0.0f) q = 4 * jdx[k] + 1;
                if (w[k].z != 0.0f) q = 4 * jdx[k] + 2;
                if (w[k].w != 0.0f) q = 4 * jdx[k] + 3;
            }
            // scalar tail (Y % 4 != 0; not hit for Y=10000)
            for (int i = (nvec << 2) + tid; i < Y; i += NT)
                if (trow[i] != 0.0f) q = i;
            if (q >= 0) s_pscore = __ldg(&irow[q]);
            __syncthreads();
        }
    }

    const float sp = s_pscore;

    // --- Phase 2: first accepted trial via warp ballot (warps 0..3) ---
    bool acc = (tid < T) && (1.0f + sc - sp >= 0.0f);
    unsigned m = __ballot_sync(0xFFFFFFFFu, acc);
    if (wid < 4 && lane == 0)
        s_first_w[wid] = m ? (wid * 32 + __ffs(m) - 1) : INT_MAX;
    __syncthreads();

    // --- Phase 3: loss for this row ---
    if (tid == 0) {
        int first = s_first_w[0];
        first = min(first, s_first_w[1]);
        first = min(first, s_first_w[2]);
        first = min(first, s_first_w[3]);
        if (first != INT_MAX) {
            const int num_trials = first + 1;
            const float L = logf((float)((Y - 1) / num_trials));
            atomicAdd(out, L * (1.0f - sp + sc_sh[first]));
        }
    }
}

extern "C" void kernel_launch(void* const* d_in, const int* in_sizes, int n_in,
                              void* d_out, int out_size) {
    const float* input  = (const float*)d_in[0];
    const float* target = (const float*)d_in[1];
    const int*   neg    = (const int*)d_in[2];
    float* out = (float*)d_out;

    const int Y = 10000;                 // fixed by problem spec
    const int B = in_sizes[0] / Y;       // 4096
    const int T = in_sizes[2] / B;       // 128

    cudaMemsetAsync(out, 0, (size_t)out_size * sizeof(float), 0);
    warp_loss_kernel<<<B, NT>>>(input, target, neg, out, Y, T);
}

// round 5
// speedup vs baseline: 1.0507x; 1.0507x over previous
#include <cuda_runtime.h>
#include <math.h>
#include <limits.h>

// WARP loss: per-row rejection sampling over pre-drawn negative candidates.
// input  [B,Y] f32, target [B,Y] f32 (one-hot), neg_candidates [B,T] i32.
// out[0] = sum_b  L_b * (1 - s_pos + s_neg),  L_b = log((Y-1)/num_trials).
//
// R5: one WARP per row. 4KB scan chunks (8 float4/lane), early exit via
// __ballot_sync -- no __syncthreads anywhere. ~28 independent row-streams
// per SM hide DRAM latency; expected scan read 21.7KB/row (vs 29.3 in R4).

#define WARPS_PER_BLOCK 4
#define FULL 0xFFFFFFFFu

__global__ __launch_bounds__(WARPS_PER_BLOCK * 32)
void warp_loss_kernel(const float* __restrict__ input,
                      const float* __restrict__ target,
                      const int*   __restrict__ neg,
                      float* __restrict__ out,
                      int B, int Y, int T) {
    const int row  = blockIdx.x * WARPS_PER_BLOCK + (threadIdx.x >> 5);
    const int lane = threadIdx.x & 31;
    if (row >= B) return;

    const float* irow = input  + (size_t)row * Y;
    const float* trow = target + (size_t)row * Y;

    // --- Phase 0: candidate gathers (independent of pos; overlap the scan) ---
    // neg row = T=128 ints = 512B; one int4 per lane covers it exactly.
    // Lane holds trials 4*lane .. 4*lane+3 (in trial order).
    const int4 c4 = __ldg(&reinterpret_cast<const int4*>(neg + (size_t)row * T)[lane]);
    const float s0 = __ldg(&irow[c4.x]);
    const float s1 = __ldg(&irow[c4.y]);
    const float s2 = __ldg(&irow[c4.z]);
    const float s3 = __ldg(&irow[c4.w]);

    // --- Phase 1: scan target for the positive; 4KB chunks, ballot early-exit ---
    const int nvec = Y >> 2;                        // 2500 for Y=10000
    const float4* tv = reinterpret_cast<const float4*>(trow);
    const float4 zero4 = make_float4(0.f, 0.f, 0.f, 0.f);

    int pos = -1;
    for (int base = 0; base < nvec; base += 256) {  // 256 float4 = 4KB chunk
        float4 v[8];
        int    idx[8];
#pragma unroll
        for (int k = 0; k < 8; k++) {               // all 8 loads in flight first
            idx[k] = base + k * 32 + lane;
            v[k] = (idx[k] < nvec) ? __ldg(&tv[idx[k]]) : zero4;
        }
        int p = -1;
#pragma unroll
        for (int k = 0; k < 8; k++) {
            if (v[k].x != 0.0f) p = 4 * idx[k];
            if (v[k].y != 0.0f) p = 4 * idx[k] + 1;
            if (v[k].z != 0.0f) p = 4 * idx[k] + 2;
            if (v[k].w != 0.0f) p = 4 * idx[k] + 3;
        }
        if (__ballot_sync(FULL, p >= 0)) {          // warp-uniform, no barrier
            pos = __reduce_min_sync(FULL, p >= 0 ? p : INT_MAX);
            break;
        }
    }
    // scalar tail for Y % 4 != 0 (not hit for Y=10000)
    if (pos < 0 && (nvec << 2) < Y) {
        int p = -1;
        for (int i = (nvec << 2) + lane; i < Y; i += 32)
            if (trow[i] != 0.0f) p = i;
        int m = __reduce_min_sync(FULL, p >= 0 ? p : INT_MAX);
        if (m != INT_MAX) pos = m;
    }
    if (pos < 0) pos = 0;                           // defensive fallback

    const float sp = __ldg(&irow[pos]);             // broadcast load (1 sector)

    // --- Phase 2: first accepted trial (warp reductions only) ---
    int myfirst = INT_MAX;
    if (1.0f + s3 - sp >= 0.0f) myfirst = 4 * lane + 3;
    if (1.0f + s2 - sp >= 0.0f) myfirst = 4 * lane + 2;
    if (1.0f + s1 - sp >= 0.0f) myfirst = 4 * lane + 1;
    if (1.0f + s0 - sp >= 0.0f) myfirst = 4 * lane;
    const int first = __reduce_min_sync(FULL, myfirst);

    // --- Phase 3: loss for this row ---
    if (first != INT_MAX) {
        const int j = first & 3;                    // warp-uniform
        const float sn_mine = (j == 0) ? s0 : (j == 1) ? s1 : (j == 2) ? s2 : s3;
        const float sn = __shfl_sync(FULL, sn_mine, first >> 2);
        if (lane == 0) {
            const int num_trials = first + 1;
            const float L = logf((float)((Y - 1) / num_trials));
            atomicAdd(out, L * (1.0f - sp + sn));
        }
    }
}

extern "C" void kernel_launch(void* const* d_in, const int* in_sizes, int n_in,
                              void* d_out, int out_size) {
    const float* input  = (const float*)d_in[0];
    const float* target = (const float*)d_in[1];
    const int*   neg    = (const int*)d_in[2];
    float* out = (float*)d_out;

    const int Y = 10000;                 // fixed by problem spec
    const int B = in_sizes[0] / Y;       // 4096
    const int T = in_sizes[2] / B;       // 128

    cudaMemsetAsync(out, 0, (size_t)out_size * sizeof(float), 0);
    const int grid = (B + WARPS_PER_BLOCK - 1) / WARPS_PER_BLOCK;
    warp_loss_kernel<<<grid, WARPS_PER_BLOCK * 32>>>(input, target, neg, out, B, Y, T);
}